// round 9
// baseline (speedup 1.0000x reference)
#include <cuda_runtime.h>
#include <cstdint>

#define ROUNDS 64
#define HID 256
#define BATCH 65536
#define TILE_M 256
#define NTILES (BATCH / TILE_M)      // 256
#define MAT_BYTES (HID * HID)        // 65536 s8 per round matrix

// Pre-converted, pre-swizzled s8 matrices (SMEM image layout), 4 MB. Lives in L2.
__device__ __align__(128) unsigned char g_mat[ROUNDS * MAT_BYTES];

// ---------------- SMEM layout (one 512-thread CTA per SM) ----------------
#define OF_NOISE 0
#define OF_A     1024
#define OF_B0    (1024 + 65536)
#define OF_B1    (OF_B0 + 65536)
#define SMEM_TOTAL (OF_B1 + 65536)   // 197632 bytes

// ---------------- helpers ----------------
__device__ __forceinline__ uint32_t smem_u32(const void* p) {
    uint32_t a;
    asm("{ .reg .u64 t; cvta.to.shared.u64 t, %1; cvt.u32.u64 %0, t; }" : "=r"(a) : "l"(p));
    return a;
}

// byte address inside a [rows x 256B] tile with 16B-chunk XOR swizzle
__device__ __forceinline__ uint32_t swz(uint32_t row, uint32_t col) {
    return row * 256u + ((((col >> 4) ^ (row & 7u)) << 4) | (col & 15u));
}

__device__ __forceinline__ void ldm_x4(uint32_t addr, uint32_t& r0, uint32_t& r1,
                                       uint32_t& r2, uint32_t& r3) {
    asm volatile("ldmatrix.sync.aligned.m8n8.x4.shared.b16 {%0,%1,%2,%3}, [%4];"
                 : "=r"(r0), "=r"(r1), "=r"(r2), "=r"(r3) : "r"(addr));
}

__device__ __forceinline__ void mma_s8(int* c, uint32_t a0, uint32_t a1, uint32_t a2,
                                       uint32_t a3, uint32_t b0, uint32_t b1) {
    asm volatile(
        "mma.sync.aligned.m16n8k32.row.col.s32.s8.s8.s32 "
        "{%0,%1,%2,%3}, {%4,%5,%6,%7}, {%8,%9}, {%0,%1,%2,%3};"
        : "+r"(c[0]), "+r"(c[1]), "+r"(c[2]), "+r"(c[3])
        : "r"(a0), "r"(a1), "r"(a2), "r"(a3), "r"(b0), "r"(b1));
}

// 512 threads fill 64KB: 8 x 16B per thread
__device__ __forceinline__ void issue_b(uint32_t dst, int r, int tid) {
    const unsigned char* src = g_mat + (size_t)r * MAT_BYTES;
#pragma unroll
    for (int j = 0; j < 8; j++) {
        uint32_t off = (uint32_t)(tid + (j << 9)) << 4;
        asm volatile("cp.async.cg.shared.global [%0], [%1], 16;"
                     :: "r"(dst + off), "l"(src + off) : "memory");
    }
}

// ---------------- Kernel 1: f32 matrices -> s8 pre-swizzled image ----------------
__global__ void cvt_mats_kernel(const float* __restrict__ m) {
    uint32_t i = blockIdx.x * 256u + threadIdx.x;       // group of 4 elements
    const float4 v = *(const float4*)(m + (size_t)i * 4);
    uint32_t e0 = v.x > 0.5f ? 0x01u : (v.x < -0.5f ? 0xFFu : 0x00u);
    uint32_t e1 = v.y > 0.5f ? 0x01u : (v.y < -0.5f ? 0xFFu : 0x00u);
    uint32_t e2 = v.z > 0.5f ? 0x01u : (v.z < -0.5f ? 0xFFu : 0x00u);
    uint32_t e3 = v.w > 0.5f ? 0x01u : (v.w < -0.5f ? 0xFFu : 0x00u);
    uint32_t pk = e0 | (e1 << 8) | (e2 << 16) | (e3 << 24);
    uint32_t idx = i << 2;
    uint32_t r = idx >> 16, n = (idx >> 8) & 255u, k = idx & 255u;
    *(uint32_t*)(g_mat + (r << 16) + swz(n, k)) = pk;   // k%16 is 4-aligned here
}

// ---------------- Kernel 2: 64 sequential rounds per 256-row tile ----------------
// 512 threads / 16 warps. Warp w -> m-group mg = w&7 (rows mg*32..+32),
// n-half nh = w>>3 (cols nh*128..+128): per-warp tile m32 x n128, identical to
// the proven 256-thread kernel. ONE shared B per round, double-buffered:
// B[r+2] issued at bottom of round r, so the round-top wait is free.
__global__ __launch_bounds__(512, 1)
void tenshash_kernel(const float* __restrict__ state,
                     const float* __restrict__ noise,
                     float* __restrict__ out) {
    extern __shared__ unsigned char smem[];
    uint32_t sb = smem_u32(smem);
    int tid = threadIdx.x, w = tid >> 5, l = tid & 31;
    int* nsm = (int*)(smem + OF_NOISE);
    const int gbase = blockIdx.x * TILE_M;
    const int mg = w & 7, nh = w >> 3;

    // stage noise[0]
    if (tid < 256) nsm[tid] = (int)noise[tid];

    // init A from state (float {0,1} -> s8), swizzled, u16-packed
    for (int i = tid; i < TILE_M * HID / 2; i += 512) {
        int row = i >> 7;
        int k = (i & 127) << 1;
        const float2 v = *(const float2*)(state + (size_t)(gbase + row) * HID + k);
        uint32_t b0 = v.x > 0.5f ? 1u : 0u;
        uint32_t b1 = v.y > 0.5f ? 1u : 0u;
        *(unsigned short*)(smem + OF_A + swz((uint32_t)row, (uint32_t)k)) =
            (unsigned short)(b0 | (b1 << 8));
    }

    // prologue: prefetch B for rounds 0 and 1
    issue_b(sb + OF_B0, 0, tid);
    asm volatile("cp.async.commit_group;" ::: "memory");
    issue_b(sb + OF_B1, 1, tid);
    asm volatile("cp.async.commit_group;" ::: "memory");

    // lane-invariant addressing pieces
    const uint32_t rowA0 = (uint32_t)(mg * 32) + (l & 15);        // A tile t=0
    const uint32_t rowA1 = rowA0 + 16;                            // A tile t=1
    const uint32_t sA0 = rowA0 & 7u, sA1 = rowA1 & 7u;
    const uint32_t aHalf = (uint32_t)(l >> 4);                    // k-chunk half
    const uint32_t bHalf = ((uint32_t)l >> 3) & 1u;
    const int erow0 = mg * 32 + (l >> 2);                         // epilogue rows
    const int ecol = nh * 128 + ((l & 3) << 1);
    const uint32_t Acur = sb + OF_A;

#pragma unroll 1
    for (int r = 0; r < ROUNDS; r++) {
        const bool last = (r == ROUNDS - 1);
        // prefetch next round's noise into a register (hidden under kk loops)
        int nz = 0;
        if (!last && tid < 256) nz = (int)noise[((r + 1) << 8) + tid];

        asm volatile("cp.async.wait_group 1;" ::: "memory");
        __syncthreads();    // B[r] ready; A stores + noise from r-1 visible
        const uint32_t Bcur = sb + ((r & 1) ? OF_B1 : OF_B0);
        uint32_t pk32[32];  // staged next-A: [ch*16 + t*8 + j]

#pragma unroll 1
        for (int ch = 0; ch < 2; ch++) {           // two 64-col n-chunks
            int acc[2][8][4];
#pragma unroll
            for (int t = 0; t < 2; t++)
#pragma unroll
                for (int j = 0; j < 8; j++)
                    acc[t][j][0] = acc[t][j][1] = acc[t][j][2] = acc[t][j][3] = 0;

#pragma unroll
            for (int kk = 0; kk < 8; kk++) {       // K = 8 x k32
                uint32_t a0[4], a1[4];
                ldm_x4(Acur + rowA0 * 256u + ((((uint32_t)(2 * kk) + aHalf) ^ sA0) << 4),
                       a0[0], a0[1], a0[2], a0[3]);
                ldm_x4(Acur + rowA1 * 256u + ((((uint32_t)(2 * kk) + aHalf) ^ sA1) << 4),
                       a1[0], a1[1], a1[2], a1[3]);
#pragma unroll
                for (int p = 0; p < 4; p++) {      // 16 cols (2 n-tiles) per x4
                    uint32_t bb[4];
                    uint32_t n = (uint32_t)(nh * 128 + ch * 64 + p * 16) +
                                 (((uint32_t)l >> 4) << 3) + (l & 7);
                    uint32_t cb = (uint32_t)(2 * kk) + bHalf;
                    ldm_x4(Bcur + n * 256u + ((cb ^ (n & 7u)) << 4),
                           bb[0], bb[1], bb[2], bb[3]);
                    mma_s8(acc[0][2 * p + 0], a0[0], a0[1], a0[2], a0[3], bb[0], bb[1]);
                    mma_s8(acc[0][2 * p + 1], a0[0], a0[1], a0[2], a0[3], bb[2], bb[3]);
                    mma_s8(acc[1][2 * p + 0], a1[0], a1[1], a1[2], a1[3], bb[0], bb[1]);
                    mma_s8(acc[1][2 * p + 1], a1[0], a1[1], a1[2], a1[3], bb[2], bb[3]);
                }
            }

            // epilogue: v = (acc + noise) % 2 (C trunc == fmod); noise hoisted over t
#pragma unroll
            for (int j = 0; j < 8; j++) {
                int col0 = ecol + (ch << 6) + (j << 3);
                int n0 = nsm[col0], n1 = nsm[col0 + 1];
#pragma unroll
                for (int t = 0; t < 2; t++) {
                    int v00 = (acc[t][j][0] + n0) % 2, v01 = (acc[t][j][1] + n1) % 2;
                    int v10 = (acc[t][j][2] + n0) % 2, v11 = (acc[t][j][3] + n1) % 2;
                    if (!last) {
                        pk32[ch * 16 + t * 8 + j] =
                            (v00 & 255) | ((v01 & 255) << 8) |
                            ((v10 & 255) << 16) | ((uint32_t)(v11 & 255) << 24);
                    } else {
                        float2 o0 = make_float2((float)v00, (float)v01);
                        float2 o1 = make_float2((float)v10, (float)v11);
                        int r0loc = erow0 + t * 16, r1loc = r0loc + 8;
                        *(float2*)(out + (size_t)(gbase + r0loc) * HID + col0) = o0;
                        *(float2*)(out + (size_t)(gbase + r1loc) * HID + col0) = o1;
                    }
                }
            }
        }

        __syncthreads();    // all reads of A, B[r], noise for round r done
        if (!last) {
            // issue B[r+2] into the buffer just freed (B[r]'s)
            if (r + 2 < ROUNDS) issue_b(sb + ((r & 1) ? OF_B1 : OF_B0), r + 2, tid);
            asm volatile("cp.async.commit_group;" ::: "memory");  // keep counts
            // store staged next-A to SMEM
#pragma unroll
            for (int ch = 0; ch < 2; ch++)
#pragma unroll
                for (int t = 0; t < 2; t++)
#pragma unroll
                    for (int j = 0; j < 8; j++) {
                        uint32_t v = pk32[ch * 16 + t * 8 + j];
                        int col0 = ecol + (ch << 6) + (j << 3);
                        int r0loc = erow0 + t * 16, r1loc = r0loc + 8;
                        *(unsigned short*)(smem + OF_A + swz((uint32_t)r0loc, (uint32_t)col0)) =
                            (unsigned short)(v & 0xFFFFu);
                        *(unsigned short*)(smem + OF_A + swz((uint32_t)r1loc, (uint32_t)col0)) =
                            (unsigned short)(v >> 16);
                    }
            // next round's noise: already in register, just store
            if (tid < 256) nsm[tid] = nz;
        }
    }
}

// ---------------- launch ----------------
extern "C" void kernel_launch(void* const* d_in, const int* in_sizes, int n_in,
                              void* d_out, int out_size) {
    const float* state = (const float*)d_in[0];
    const float* mats  = (const float*)d_in[1];
    const float* noise = (const float*)d_in[2];
    float* out = (float*)d_out;

    cvt_mats_kernel<<<ROUNDS * MAT_BYTES / 4 / 256, 256>>>(mats);

    cudaFuncSetAttribute(tenshash_kernel,
                         cudaFuncAttributeMaxDynamicSharedMemorySize, SMEM_TOTAL);
    tenshash_kernel<<<NTILES, 512, SMEM_TOTAL>>>(state, noise, out);
}

// round 11
// speedup vs baseline: 1.0657x; 1.0657x over previous
#include <cuda_runtime.h>
#include <cstdint>

#define ROUNDS 64
#define HID 256
#define BATCH 65536
#define TILE_M 128
#define NTILES (BATCH / TILE_M)      // 512
#define MAT_BYTES (HID * HID)        // 65536 s8 per round matrix

// Pre-converted, pre-swizzled s8 matrices (SMEM image layout), 4 MB. Lives in L2.
__device__ __align__(128) unsigned char g_mat[ROUNDS * MAT_BYTES];
// Per-(round, thread) packed noise bits: bit (ch*16 + j*2 + h) = noise[col(ch,j,h)].
__device__ __align__(128) uint32_t g_noise[ROUNDS * 256];

// ---------------- SMEM layout (fits 2 CTAs/SM) ----------------
#define OF_A     0
#define OF_B     32768
#define SMEM_TOTAL (32768 + 65536)   // 98304 bytes

// ---------------- helpers ----------------
__device__ __forceinline__ uint32_t smem_u32(const void* p) {
    uint32_t a;
    asm("{ .reg .u64 t; cvta.to.shared.u64 t, %1; cvt.u32.u64 %0, t; }" : "=r"(a) : "l"(p));
    return a;
}

// byte address inside a [rows x 256B] tile with 16B-chunk XOR swizzle
__device__ __forceinline__ uint32_t swz(uint32_t row, uint32_t col) {
    return row * 256u + ((((col >> 4) ^ (row & 7u)) << 4) | (col & 15u));
}

__device__ __forceinline__ void ldm_x4(uint32_t addr, uint32_t& r0, uint32_t& r1,
                                       uint32_t& r2, uint32_t& r3) {
    asm volatile("ldmatrix.sync.aligned.m8n8.x4.shared.b16 {%0,%1,%2,%3}, [%4];"
                 : "=r"(r0), "=r"(r1), "=r"(r2), "=r"(r3) : "r"(addr));
}

__device__ __forceinline__ void mma_s8(int* c, uint32_t a0, uint32_t a1, uint32_t a2,
                                       uint32_t a3, uint32_t b0, uint32_t b1) {
    asm volatile(
        "mma.sync.aligned.m16n8k32.row.col.s32.s8.s8.s32 "
        "{%0,%1,%2,%3}, {%4,%5,%6,%7}, {%8,%9}, {%0,%1,%2,%3};"
        : "+r"(c[0]), "+r"(c[1]), "+r"(c[2]), "+r"(c[3])
        : "r"(a0), "r"(a1), "r"(a2), "r"(a3), "r"(b0), "r"(b1));
}

// group (128 threads) fills its own 32KB B half: 16 x 16B per thread
__device__ __forceinline__ void issue_bhalf(uint32_t dst, const unsigned char* src,
                                            int g_tid) {
#pragma unroll
    for (int j = 0; j < 16; j++) {
        uint32_t off = (uint32_t)(g_tid + (j << 7)) << 4;
        asm volatile("cp.async.cg.shared.global [%0], [%1], 16;"
                     :: "r"(dst + off), "l"(src + off) : "memory");
    }
}

// ---------------- Kernel 1a: f32 matrices -> s8 pre-swizzled image ----------------
__global__ void cvt_mats_kernel(const float* __restrict__ m) {
    uint32_t i = blockIdx.x * 256u + threadIdx.x;       // group of 4 elements
    const float4 v = *(const float4*)(m + (size_t)i * 4);
    uint32_t e0 = v.x > 0.5f ? 0x01u : (v.x < -0.5f ? 0xFFu : 0x00u);
    uint32_t e1 = v.y > 0.5f ? 0x01u : (v.y < -0.5f ? 0xFFu : 0x00u);
    uint32_t e2 = v.z > 0.5f ? 0x01u : (v.z < -0.5f ? 0xFFu : 0x00u);
    uint32_t e3 = v.w > 0.5f ? 0x01u : (v.w < -0.5f ? 0xFFu : 0x00u);
    uint32_t pk = e0 | (e1 << 8) | (e2 << 16) | (e3 << 24);
    uint32_t idx = i << 2;
    uint32_t r = idx >> 16, n = (idx >> 8) & 255u, k = idx & 255u;
    *(uint32_t*)(g_mat + (r << 16) + swz(n, k)) = pk;   // k%16 is 4-aligned here
}

// ---------------- Kernel 1b: f32 noise -> per-thread packed bits ----------------
__global__ void cvt_noise_kernel(const float* __restrict__ nz) {
    int r = blockIdx.x;          // 64
    int tid = threadIdx.x;       // 256
    int w = tid >> 5, l = tid & 31;
    int nh = w >> 2;
    int ecol = nh * 128 + ((l & 3) << 1);
    uint32_t acc = 0;
    for (int ch = 0; ch < 2; ch++)
        for (int j = 0; j < 8; j++) {
            int col = ecol + (ch << 6) + (j << 3);
            uint32_t b0 = nz[r * HID + col] > 0.5f ? 1u : 0u;
            uint32_t b1 = nz[r * HID + col + 1] > 0.5f ? 1u : 0u;
            acc |= b0 << (ch * 16 + j * 2);
            acc |= b1 << (ch * 16 + j * 2 + 1);
        }
    g_noise[r * 256 + tid] = acc;
}

// ---------------- Kernel 2: 64 sequential rounds per 128-row tile ----------------
// Warp tiling: warp w -> mg = w&3 (A rows mg*32..+32), nh = w>>2 (B rows/out cols
// nh*128..+128). A rows are PRIVATE to pair {(mg,0),(mg,1)}; B half PRIVATE to
// the 4-warp nh group. No CTA-wide barriers in the round loop:
//   pair bars (64 thr, id 1+mg) cover the A read/write hazard,
//   group bars (128 thr, id 5+nh) cover B-half fill visibility + refill safety.
// Noise comes from g_noise as one packed u32 per thread per round (registers).
__global__ __launch_bounds__(256, 2)
void tenshash_kernel(const float* __restrict__ state,
                     float* __restrict__ out) {
    extern __shared__ unsigned char smem[];
    uint32_t sb = smem_u32(smem);
    int tid = threadIdx.x, w = tid >> 5, l = tid & 31;
    const int gbase = blockIdx.x * TILE_M;
    const int mg = w & 3, nh = w >> 2;
    const int g_tid = mg * 32 + l;                    // index within nh group

    // init A from state (float {0,1} -> s8), swizzled, u16-packed
    for (int i = tid; i < TILE_M * HID / 2; i += 256) {
        int row = i >> 7;
        int k = (i & 127) << 1;
        const float2 v = *(const float2*)(state + (size_t)(gbase + row) * HID + k);
        uint32_t b0 = v.x > 0.5f ? 1u : 0u;
        uint32_t b1 = v.y > 0.5f ? 1u : 0u;
        *(unsigned short*)(smem + OF_A + swz((uint32_t)row, (uint32_t)k)) =
            (unsigned short)(b0 | (b1 << 8));
    }

    // prologue: each group fills its own B half for round 0
    issue_bhalf(sb + OF_B + (uint32_t)nh * 32768u,
                g_mat + (size_t)nh * 32768u, g_tid);
    asm volatile("cp.async.commit_group;" ::: "memory");
    __syncthreads();    // A init visible to all

    // lane-invariant addressing pieces
    const uint32_t rowA0 = (uint32_t)(mg * 32) + (l & 15);        // A tile t=0
    const uint32_t rowA1 = rowA0 + 16;                            // A tile t=1
    const uint32_t sA0 = rowA0 & 7u, sA1 = rowA1 & 7u;
    const uint32_t aHalf = (uint32_t)(l >> 4);                    // k-chunk half
    const uint32_t bHalf = ((uint32_t)l >> 3) & 1u;
    const int erow0 = mg * 32 + (l >> 2);                         // epilogue rows
    const int ecol = nh * 128 + ((l & 3) << 1);
    const uint32_t Acur = sb + OF_A;
    const uint32_t Bcur = sb + OF_B;

#pragma unroll 1
    for (int r = 0; r < ROUNDS; r++) {
        const bool last = (r == ROUNDS - 1);
        const uint32_t nz = g_noise[(r << 8) + tid];  // packed noise bits (L2 hit)

        asm volatile("cp.async.wait_group 0;" ::: "memory");      // own fills done
        asm volatile("bar.sync %0, 128;" :: "r"(5 + nh) : "memory"); // group fills visible
        uint32_t pk32[32];  // staged next-A: [ch*16 + t*8 + j]

#pragma unroll 1
        for (int ch = 0; ch < 2; ch++) {           // two 64-col n-chunks
            int acc[2][8][4];
#pragma unroll
            for (int t = 0; t < 2; t++)
#pragma unroll
                for (int j = 0; j < 8; j++)
                    acc[t][j][0] = acc[t][j][1] = acc[t][j][2] = acc[t][j][3] = 0;

#pragma unroll
            for (int kk = 0; kk < 8; kk++) {       // K = 8 x k32
                uint32_t a0[4], a1[4];
                ldm_x4(Acur + rowA0 * 256u + ((((uint32_t)(2 * kk) + aHalf) ^ sA0) << 4),
                       a0[0], a0[1], a0[2], a0[3]);
                ldm_x4(Acur + rowA1 * 256u + ((((uint32_t)(2 * kk) + aHalf) ^ sA1) << 4),
                       a1[0], a1[1], a1[2], a1[3]);
#pragma unroll
                for (int p = 0; p < 4; p++) {      // 16 cols (2 n-tiles) per x4
                    uint32_t bb[4];
                    uint32_t n = (uint32_t)(nh * 128 + ch * 64 + p * 16) +
                                 (((uint32_t)l >> 4) << 3) + (l & 7);
                    uint32_t cb = (uint32_t)(2 * kk) + bHalf;
                    ldm_x4(Bcur + n * 256u + ((cb ^ (n & 7u)) << 4),
                           bb[0], bb[1], bb[2], bb[3]);
                    mma_s8(acc[0][2 * p + 0], a0[0], a0[1], a0[2], a0[3], bb[0], bb[1]);
                    mma_s8(acc[0][2 * p + 1], a0[0], a0[1], a0[2], a0[3], bb[2], bb[3]);
                    mma_s8(acc[1][2 * p + 0], a1[0], a1[1], a1[2], a1[3], bb[0], bb[1]);
                    mma_s8(acc[1][2 * p + 1], a1[0], a1[1], a1[2], a1[3], bb[2], bb[3]);
                }
            }

            // epilogue: v = (acc + noise_bit) % 2 (C trunc == fmod); noise from nz reg
#pragma unroll
            for (int j = 0; j < 8; j++) {
                int n0 = (int)((nz >> (ch * 16 + j * 2)) & 1u);
                int n1 = (int)((nz >> (ch * 16 + j * 2 + 1)) & 1u);
#pragma unroll
                for (int t = 0; t < 2; t++) {
                    int v00 = (acc[t][j][0] + n0) % 2, v01 = (acc[t][j][1] + n1) % 2;
                    int v10 = (acc[t][j][2] + n0) % 2, v11 = (acc[t][j][3] + n1) % 2;
                    if (!last) {
                        pk32[ch * 16 + t * 8 + j] =
                            (v00 & 255) | ((v01 & 255) << 8) |
                            ((v10 & 255) << 16) | ((uint32_t)(v11 & 255) << 24);
                    } else {
                        int col0 = ecol + (ch << 6) + (j << 3);
                        float2 o0 = make_float2((float)v00, (float)v01);
                        float2 o1 = make_float2((float)v10, (float)v11);
                        int r0loc = erow0 + t * 16, r1loc = r0loc + 8;
                        *(float2*)(out + (size_t)(gbase + r0loc) * HID + col0) = o0;
                        *(float2*)(out + (size_t)(gbase + r1loc) * HID + col0) = o1;
                    }
                }
            }
        }

        if (last) break;

        // group done reading its B half -> refill it for round r+1
        asm volatile("bar.sync %0, 128;" :: "r"(5 + nh) : "memory");
        issue_bhalf(sb + OF_B + (uint32_t)nh * 32768u,
                    g_mat + (size_t)(r + 1) * MAT_BYTES + (size_t)nh * 32768u, g_tid);
        asm volatile("cp.async.commit_group;" ::: "memory");

        // pair done reading A[mg] -> store staged next-A, then make it visible
        asm volatile("bar.sync %0, 64;" :: "r"(1 + mg) : "memory");
#pragma unroll
        for (int ch = 0; ch < 2; ch++)
#pragma unroll
            for (int t = 0; t < 2; t++)
#pragma unroll
                for (int j = 0; j < 8; j++) {
                    uint32_t v = pk32[ch * 16 + t * 8 + j];
                    int col0 = ecol + (ch << 6) + (j << 3);
                    int r0loc = erow0 + t * 16, r1loc = r0loc + 8;
                    *(unsigned short*)(smem + OF_A + swz((uint32_t)r0loc, (uint32_t)col0)) =
                        (unsigned short)(v & 0xFFFFu);
                    *(unsigned short*)(smem + OF_A + swz((uint32_t)r1loc, (uint32_t)col0)) =
                        (unsigned short)(v >> 16);
                }
        asm volatile("bar.sync %0, 64;" :: "r"(1 + mg) : "memory");
    }
}

// ---------------- launch ----------------
extern "C" void kernel_launch(void* const* d_in, const int* in_sizes, int n_in,
                              void* d_out, int out_size) {
    const float* state = (const float*)d_in[0];
    const float* mats  = (const float*)d_in[1];
    const float* noise = (const float*)d_in[2];
    float* out = (float*)d_out;

    cvt_mats_kernel<<<ROUNDS * MAT_BYTES / 4 / 256, 256>>>(mats);
    cvt_noise_kernel<<<ROUNDS, 256>>>(noise);

    cudaFuncSetAttribute(tenshash_kernel,
                         cudaFuncAttributeMaxDynamicSharedMemorySize, SMEM_TOTAL);
    tenshash_kernel<<<NTILES, 256, SMEM_TOTAL>>>(state, out);
}